// round 15
// baseline (speedup 1.0000x reference)
#include <cuda_runtime.h>

// out[b] = -(inp[b,:] . quad)^2 + inp[b,:] . linw + bias
// B = 16384, D = 4096, fp32. 256 MiB streaming read.
//
// FINAL (converged, R14): grid 1024 x 16 rows/block, 256 threads (8 warps),
// warp-per-column-chunk, weights in 32 registers, 4 independent LDG.128.CS
// per warp-row (__ldcs: inp is read exactly once -> evict-first), deferred
// per-lane reduction so the steady loop is 4 LDG + 32 FMA + 1 STS only.
// regs = 64 = exactly 4 blocks/SM (full register file).
//
// Convergence evidence (14 rounds):
//  - LDG / __ldcs / cp.async / TMA all pin at 6.0-6.3 TB/s: the
//    path-independent LTS/HBM streaming ceiling (~78% of 8 TB/s spec).
//  - Wave scan {1, 1.73, 3.46} -> {47.2, 45.06, 46.4} us; 1.73 optimal.
//  - 64-reg boundary sharp: unroll4/68regs -> 53us; 80 regs -> 45.5us.
//  - Achievable floor ~ 268MB / 6.25TB/s ~ 43us; this runs at ~96% of it
//    (44.5us device-side, 45.1us harness).

#ifndef D_DIM
#define D_DIM 4096
#endif

constexpr int THREADS        = 256;            // 8 warps
constexpr int WARPS          = THREADS / 32;   // 8
constexpr int F4_PER_LANE    = (D_DIM / WARPS) / 4 / 32;  // 4
constexpr int ROWS_PER_BLOCK = 16;

__global__ __launch_bounds__(THREADS)
void skinny_quad_kernel(const float* __restrict__ inp,
                        const float* __restrict__ quad,
                        const float* __restrict__ linw,
                        const float* __restrict__ linb,
                        float* __restrict__ out,
                        int B)
{
    // per-lane partials: [row][256 lanes] (float2 = sq, sl) -> 32KB
    __shared__ float2 s_part[ROWS_PER_BLOCK][THREADS];

    const int tid  = threadIdx.x;
    const int lane = tid & 31;
    const int warp = tid >> 5;

    // warp's column chunk: 128 float4 (512 floats)
    const int cbase = warp * (D_DIM / WARPS / 4);

    // Weights in registers, loaded once per block (default/cached policy)
    const float4* __restrict__ gq = reinterpret_cast<const float4*>(quad) + cbase;
    const float4* __restrict__ gl = reinterpret_cast<const float4*>(linw) + cbase;
    float4 q[F4_PER_LANE], l[F4_PER_LANE];
    #pragma unroll
    for (int i = 0; i < F4_PER_LANE; ++i) {
        q[i] = gq[i * 32 + lane];
        l[i] = gl[i * 32 + lane];
    }

    const int row0 = blockIdx.x * ROWS_PER_BLOCK;

    #pragma unroll 2
    for (int r = 0; r < ROWS_PER_BLOCK; ++r) {
        const float4* __restrict__ xr =
            reinterpret_cast<const float4*>(inp + (size_t)(row0 + r) * D_DIM) + cbase;

        float4 x[F4_PER_LANE];
        #pragma unroll
        for (int i = 0; i < F4_PER_LANE; ++i)
            x[i] = __ldcs(&xr[i * 32 + lane]);   // streaming: evict-first

        float sq = 0.f, sl = 0.f;
        #pragma unroll
        for (int i = 0; i < F4_PER_LANE; ++i) {
            sq = fmaf(x[i].x, q[i].x, sq);
            sq = fmaf(x[i].y, q[i].y, sq);
            sq = fmaf(x[i].z, q[i].z, sq);
            sq = fmaf(x[i].w, q[i].w, sq);
            sl = fmaf(x[i].x, l[i].x, sl);
            sl = fmaf(x[i].y, l[i].y, sl);
            sl = fmaf(x[i].z, l[i].z, sl);
            sl = fmaf(x[i].w, l[i].w, sl);
        }

        // fire-and-forget per-lane partial; no shuffles in the stream loop
        s_part[r][tid] = make_float2(sq, sl);
    }

    __syncthreads();

    // Block-wide reduction: 16 threads per row, each sums 16 partials,
    // then a 4-stage shuffle reduce within the 16-thread subgroup.
    {
        const int row = tid >> 4;        // 0..15
        const int sub = tid & 15;        // 0..15

        float sq = 0.f, sl = 0.f;
        #pragma unroll
        for (int k = 0; k < THREADS / 16; ++k) {
            const float2 p = s_part[row][sub + k * 16];
            sq += p.x;
            sl += p.y;
        }

        #pragma unroll
        for (int off = 8; off > 0; off >>= 1) {
            sq += __shfl_down_sync(0xFFFFFFFFu, sq, off, 16);
            sl += __shfl_down_sync(0xFFFFFFFFu, sl, off, 16);
        }

        if (sub == 0) {
            const int orow = row0 + row;
            if (orow < B) {
                const float bias = *linb;
                out[orow] = fmaf(-sq, sq, sl + bias);
            }
        }
    }
}

extern "C" void kernel_launch(void* const* d_in, const int* in_sizes, int n_in,
                              void* d_out, int out_size)
{
    const float* inp  = (const float*)d_in[0];   // (B, D)
    const float* quad = (const float*)d_in[1];   // (D, 1)
    const float* linw = (const float*)d_in[2];   // (1, D)
    const float* linb = (const float*)d_in[3];   // (1,)
    float* out = (float*)d_out;

    const int B = in_sizes[0] / D_DIM;
    const int grid = (B + ROWS_PER_BLOCK - 1) / ROWS_PER_BLOCK;

    skinny_quad_kernel<<<grid, THREADS>>>(inp, quad, linw, linb, out, B);
}